// round 2
// baseline (speedup 1.0000x reference)
#include <cuda_runtime.h>

#define N_SRC 60000
#define N_DST 30000
#define DEG   32
#define K_SEL 16
#define F     128
#define E     64

// Scratch: per-source sigmoid(x . W_dist[:,0] + b_dist[0])
__device__ float g_sig[N_SRC];

// ---------------------------------------------------------------------------
// Kernel 1: warp-per-node. Computes g_sig for all 60000 source nodes and
// score_logits (both columns) for the 30000 dst nodes.
// ---------------------------------------------------------------------------
__global__ void score_kernel(const float* __restrict__ x,
                             const float* __restrict__ W_dist,
                             const float* __restrict__ b_dist,
                             float* __restrict__ out_scores) {
    __shared__ float sw[F * 2];
    int tid = threadIdx.x;
    if (tid < F * 2) sw[tid] = W_dist[tid];
    __syncthreads();

    int warp = tid >> 5;
    int lane = tid & 31;
    int node = blockIdx.x * (blockDim.x >> 5) + warp;
    if (node >= N_SRC) return;

    // 512B coalesced row load: lane l takes features [4l, 4l+4)
    float4 x4 = reinterpret_cast<const float4*>(x + (size_t)node * F)[lane];
    int fb = lane * 4;
    float s0 = x4.x * sw[(fb + 0) * 2] + x4.y * sw[(fb + 1) * 2]
             + x4.z * sw[(fb + 2) * 2] + x4.w * sw[(fb + 3) * 2];
    float s1 = x4.x * sw[(fb + 0) * 2 + 1] + x4.y * sw[(fb + 1) * 2 + 1]
             + x4.z * sw[(fb + 2) * 2 + 1] + x4.w * sw[(fb + 3) * 2 + 1];

    #pragma unroll
    for (int off = 16; off; off >>= 1) {
        s0 += __shfl_xor_sync(0xFFFFFFFFu, s0, off);
        s1 += __shfl_xor_sync(0xFFFFFFFFu, s1, off);
    }

    if (lane == 0) {
        float l0 = s0 + b_dist[0];
        g_sig[node] = 1.0f / (1.0f + expf(-l0));
        if (node < N_DST) {
            out_scores[(size_t)node * 2 + 0] = l0;
            out_scores[(size_t)node * 2 + 1] = s1 + b_dist[1];
        }
    }
}

// ---------------------------------------------------------------------------
// Kernel 2: block-per-dst (128 threads). Stable top-K selection on
// precomputed sigmoid scalars, float4 gather of the 16 selected rows,
// then the fused SAGE MLP with float4 weight loads.
// ---------------------------------------------------------------------------
__global__ void __launch_bounds__(128)
sage_kernel(const float* __restrict__ x,
            const int*   __restrict__ neighbors,
            const float* __restrict__ W_self,
            const float* __restrict__ W_neigh,
            const float* __restrict__ b_sage,
            const float* __restrict__ W_out,
            const float* __restrict__ b_out,
            float* __restrict__ out_logits) {
    int i    = blockIdx.x;
    int tid  = threadIdx.x;
    int warp = tid >> 5;
    int lane = tid & 31;

    __shared__ float  sdiff[DEG];
    __shared__ int    snb[DEG];
    __shared__ int    ssel[K_SEL];
    __shared__ float  sxd[F];
    __shared__ float  shn[F];
    __shared__ float4 sgp[4][32];      // gather partials
    __shared__ float4 spart4[8][16];   // MLP partials
    __shared__ float  sh[E];

    float t = g_sig[i];

    if (warp == 0) {
        int nb = neighbors[(size_t)i * DEG + lane];
        snb[lane]   = nb;
        sdiff[lane] = fabsf(t - g_sig[nb]);
    } else if (warp == 1) {
        // dst row load overlapped with neighbor scoring
        reinterpret_cast<float4*>(sxd)[lane] =
            reinterpret_cast<const float4*>(x + (size_t)i * F)[lane];
    }
    __syncthreads();

    if (warp == 0) {
        float d = sdiff[lane];
        int rank = 0;
        #pragma unroll
        for (int k = 0; k < DEG; k++) {
            float dk = sdiff[k];
            rank += (dk < d) || (dk == d && k < lane);
        }
        // Ranks are a permutation of 0..31 -> ranks 0..15 fill ssel exactly,
        // matching jax.lax.top_k(-diff) stable tie order.
        if (rank < K_SEL) ssel[rank] = snb[lane];
    }
    __syncthreads();

    // float4 gather: warp w loads whole rows ssel[w], ssel[w+4], ssel[w+8],
    // ssel[w+12] (each row = 32 lanes x 16B = 512B, fully coalesced).
    {
        float4 acc = make_float4(0.f, 0.f, 0.f, 0.f);
        #pragma unroll
        for (int s = 0; s < 4; s++) {
            int row = ssel[warp + 4 * s];
            float4 v = reinterpret_cast<const float4*>(x + (size_t)row * F)[lane];
            acc.x += v.x; acc.y += v.y; acc.z += v.z; acc.w += v.w;
        }
        sgp[warp][lane] = acc;
    }
    __syncthreads();

    if (warp == 0) {
        float4 a = sgp[0][lane], b = sgp[1][lane],
               c = sgp[2][lane], d = sgp[3][lane];
        float4 m;
        m.x = (a.x + b.x + c.x + d.x) * (1.0f / K_SEL);
        m.y = (a.y + b.y + c.y + d.y) * (1.0f / K_SEL);
        m.z = (a.z + b.z + c.z + d.z) * (1.0f / K_SEL);
        m.w = (a.w + b.w + c.w + d.w) * (1.0f / K_SEL);
        reinterpret_cast<float4*>(shn)[lane] = m;
    }
    __syncthreads();

    // MLP: thread = (eg = 4 consecutive e, part = 16-wide f slice).
    // Weight reads are float4 (L1-resident across blocks), sxd/shn are
    // warp-broadcast LDS.
    {
        int eg   = tid & 15;
        int part = tid >> 4;
        int f0   = part * 16;
        const float4* Ws = reinterpret_cast<const float4*>(W_self)  + eg;
        const float4* Wn = reinterpret_cast<const float4*>(W_neigh) + eg;
        float4 a = make_float4(0.f, 0.f, 0.f, 0.f);
        #pragma unroll
        for (int f = 0; f < 16; f++) {
            int ff = f0 + f;
            float xs = sxd[ff];
            float hn = shn[ff];
            float4 ws = Ws[ff * (E / 4)];
            float4 wn = Wn[ff * (E / 4)];
            a.x += xs * ws.x + hn * wn.x;
            a.y += xs * ws.y + hn * wn.y;
            a.z += xs * ws.z + hn * wn.z;
            a.w += xs * ws.w + hn * wn.w;
        }
        spart4[part][eg] = a;
    }
    __syncthreads();

    if (tid < 16) {
        float4 h = make_float4(0.f, 0.f, 0.f, 0.f);
        #pragma unroll
        for (int p = 0; p < 8; p++) {
            float4 v = spart4[p][tid];
            h.x += v.x; h.y += v.y; h.z += v.z; h.w += v.w;
        }
        float4 bs = reinterpret_cast<const float4*>(b_sage)[tid];
        sh[tid * 4 + 0] = fmaxf(h.x + bs.x, 0.0f);
        sh[tid * 4 + 1] = fmaxf(h.y + bs.y, 0.0f);
        sh[tid * 4 + 2] = fmaxf(h.z + bs.z, 0.0f);
        sh[tid * 4 + 3] = fmaxf(h.w + bs.w, 0.0f);
    }
    __syncthreads();

    if (tid < 2) {
        float a = b_out[tid];
        #pragma unroll
        for (int e = 0; e < E; e++) a += sh[e] * W_out[e * 2 + tid];
        out_logits[(size_t)i * 2 + tid] = a;
    }
}

// ---------------------------------------------------------------------------
extern "C" void kernel_launch(void* const* d_in, const int* in_sizes, int n_in,
                              void* d_out, int out_size) {
    const float* x         = (const float*)d_in[0];
    const int*   neighbors = (const int*)  d_in[1];
    const float* W_dist    = (const float*)d_in[2];
    const float* b_dist    = (const float*)d_in[3];
    const float* W_self    = (const float*)d_in[4];
    const float* W_neigh   = (const float*)d_in[5];
    const float* b_sage    = (const float*)d_in[6];
    const float* W_out     = (const float*)d_in[7];
    const float* b_out     = (const float*)d_in[8];

    float* out        = (float*)d_out;
    float* out_logits = out;                 // [N_DST, 2]
    float* out_scores = out + 2 * N_DST;     // [N_DST, 2]

    // 8 warps/block -> 60000/8 = 7500 blocks exactly.
    score_kernel<<<N_SRC / 8, 256>>>(x, W_dist, b_dist, out_scores);
    sage_kernel<<<N_DST, 128>>>(x, neighbors, W_self, W_neigh, b_sage,
                                W_out, b_out, out_logits);
}

// round 9
// speedup vs baseline: 1.7827x; 1.7827x over previous
#include <cuda_runtime.h>

#define N_SRC 60000
#define N_DST 30000
#define DEG   32
#define K_SEL 16
#define F     128
#define E     64
#define NB    8      // dst nodes per block in sage_kernel

// Scratch: per-source sigmoid(x . W_dist[:,0] + b_dist[0])
__device__ float g_sig[N_SRC];

// ---------------------------------------------------------------------------
// Kernel 1: warp-per-node. Computes g_sig for all 60000 source nodes and
// score_logits (both columns) for the 30000 dst nodes.
// ---------------------------------------------------------------------------
__global__ void score_kernel(const float* __restrict__ x,
                             const float* __restrict__ W_dist,
                             const float* __restrict__ b_dist,
                             float* __restrict__ out_scores) {
    __shared__ float sw[F * 2];
    int tid = threadIdx.x;
    if (tid < F * 2) sw[tid] = W_dist[tid];
    __syncthreads();

    int warp = tid >> 5;
    int lane = tid & 31;
    int node = blockIdx.x * (blockDim.x >> 5) + warp;
    if (node >= N_SRC) return;

    float4 x4 = reinterpret_cast<const float4*>(x + (size_t)node * F)[lane];
    int fb = lane * 4;
    float s0 = x4.x * sw[(fb + 0) * 2] + x4.y * sw[(fb + 1) * 2]
             + x4.z * sw[(fb + 2) * 2] + x4.w * sw[(fb + 3) * 2];
    float s1 = x4.x * sw[(fb + 0) * 2 + 1] + x4.y * sw[(fb + 1) * 2 + 1]
             + x4.z * sw[(fb + 2) * 2 + 1] + x4.w * sw[(fb + 3) * 2 + 1];

    #pragma unroll
    for (int off = 16; off; off >>= 1) {
        s0 += __shfl_xor_sync(0xFFFFFFFFu, s0, off);
        s1 += __shfl_xor_sync(0xFFFFFFFFu, s1, off);
    }

    if (lane == 0) {
        float l0 = s0 + b_dist[0];
        g_sig[node] = 1.0f / (1.0f + expf(-l0));
        if (node < N_DST) {
            out_scores[(size_t)node * 2 + 0] = l0;
            out_scores[(size_t)node * 2 + 1] = s1 + b_dist[1];
        }
    }
}

// ---------------------------------------------------------------------------
// Kernel 2: 8 dst nodes per 256-thread block.
//   phase 1: warp d scores + stable-ranks dst d's 32 neighbors (shuffle rank)
//   phase 2: warp d gathers its 16 selected rows (float4) + dst row
//   phase 3: MLP, thread=(eg: 4 e's via float4, part: 8-f slice); each
//            weight float4 loaded once per block -> 8x weight amortization
//   phase 4: cross-part reduce + relu + tiny output projection
// ---------------------------------------------------------------------------
__global__ void __launch_bounds__(256)
sage_kernel(const float* __restrict__ x,
            const int*   __restrict__ neighbors,
            const float* __restrict__ W_self,
            const float* __restrict__ W_neigh,
            const float* __restrict__ b_sage,
            const float* __restrict__ W_out,
            const float* __restrict__ b_out,
            float* __restrict__ out_logits) {
    int tid  = threadIdx.x;
    int warp = tid >> 5;
    int lane = tid & 31;
    int base = blockIdx.x * NB;

    __shared__ int    ssel[NB][K_SEL];
    __shared__ float  sxd[NB][F];
    __shared__ float  shn[NB][F];
    __shared__ float4 spart[16][NB][16];   // [part][d][eg]  32KB
    __shared__ float  sh[NB][E];

    // ---- phase 1: neighbor scoring + stable top-K rank (warp per dst) ----
    {
        int d  = warp;
        int nb = neighbors[(size_t)(base + d) * DEG + lane];
        float t  = g_sig[base + d];
        float df = fabsf(t - g_sig[nb]);
        int rank = 0;
        #pragma unroll
        for (int k = 0; k < DEG; k++) {
            float dk = __shfl_sync(0xFFFFFFFFu, df, k);
            rank += (dk < df) || (dk == df && k < lane);
        }
        // ranks are a permutation of 0..31: ranks 0..15 fill ssel exactly,
        // reproducing jax.lax.top_k(-diff) stable tie order.
        if (rank < K_SEL) ssel[d][rank] = nb;
    }
    // ssel[d] is produced and consumed by the same warp -> warp sync suffices.
    __syncwarp();

    // ---- phase 2: gather 16 selected rows + dst row (warp per dst) ----
    {
        int d = warp;
        float4 acc = make_float4(0.f, 0.f, 0.f, 0.f);
        #pragma unroll
        for (int s = 0; s < K_SEL; s++) {
            int r = ssel[d][s];
            float4 v = reinterpret_cast<const float4*>(x + (size_t)r * F)[lane];
            acc.x += v.x; acc.y += v.y; acc.z += v.z; acc.w += v.w;
        }
        float4 m;
        m.x = acc.x * (1.0f / K_SEL); m.y = acc.y * (1.0f / K_SEL);
        m.z = acc.z * (1.0f / K_SEL); m.w = acc.w * (1.0f / K_SEL);
        reinterpret_cast<float4*>(shn[d])[lane] = m;
        reinterpret_cast<float4*>(sxd[d])[lane] =
            reinterpret_cast<const float4*>(x + (size_t)(base + d) * F)[lane];
    }
    __syncthreads();

    // ---- phase 3: MLP partials. eg = 4 consecutive e (float4 weights),
    //      part = 8-wide f slice. Weights read once per block total. ----
    {
        int eg   = tid & 15;
        int part = tid >> 4;
        const float4* Ws = reinterpret_cast<const float4*>(W_self);   // [f][16]
        const float4* Wn = reinterpret_cast<const float4*>(W_neigh);
        float4 a[NB];
        #pragma unroll
        for (int d = 0; d < NB; d++) a[d] = make_float4(0.f, 0.f, 0.f, 0.f);

        #pragma unroll
        for (int f0 = 0; f0 < 8; f0++) {
            int f = part * 8 + f0;
            float4 ws = Ws[f * (E / 4) + eg];
            float4 wn = Wn[f * (E / 4) + eg];
            #pragma unroll
            for (int d = 0; d < NB; d++) {
                float xs = sxd[d][f];
                float hn = shn[d][f];
                a[d].x += xs * ws.x + hn * wn.x;
                a[d].y += xs * ws.y + hn * wn.y;
                a[d].z += xs * ws.z + hn * wn.z;
                a[d].w += xs * ws.w + hn * wn.w;
            }
        }
        #pragma unroll
        for (int d = 0; d < NB; d++) spart[part][d][eg] = a[d];
    }
    __syncthreads();

    // ---- phase 4a: reduce 16 parts, bias, relu ----
    if (tid < NB * 16) {
        int d  = tid >> 4;
        int eg = tid & 15;
        float4 h = make_float4(0.f, 0.f, 0.f, 0.f);
        #pragma unroll
        for (int p = 0; p < 16; p++) {
            float4 v = spart[p][d][eg];
            h.x += v.x; h.y += v.y; h.z += v.z; h.w += v.w;
        }
        float4 bs = reinterpret_cast<const float4*>(b_sage)[eg];
        sh[d][eg * 4 + 0] = fmaxf(h.x + bs.x, 0.0f);
        sh[d][eg * 4 + 1] = fmaxf(h.y + bs.y, 0.0f);
        sh[d][eg * 4 + 2] = fmaxf(h.z + bs.z, 0.0f);
        sh[d][eg * 4 + 3] = fmaxf(h.w + bs.w, 0.0f);
    }
    __syncthreads();

    // ---- phase 4b: output projection (E=64 -> C=2) ----
    if (tid < NB * 2) {
        int d = tid >> 1;
        int c = tid & 1;
        float a = b_out[c];
        #pragma unroll
        for (int e = 0; e < E; e++) a += sh[d][e] * W_out[e * 2 + c];
        out_logits[(size_t)(base + d) * 2 + c] = a;
    }
}

// ---------------------------------------------------------------------------
extern "C" void kernel_launch(void* const* d_in, const int* in_sizes, int n_in,
                              void* d_out, int out_size) {
    const float* x         = (const float*)d_in[0];
    const int*   neighbors = (const int*)  d_in[1];
    const float* W_dist    = (const float*)d_in[2];
    const float* b_dist    = (const float*)d_in[3];
    const float* W_self    = (const float*)d_in[4];
    const float* W_neigh   = (const float*)d_in[5];
    const float* b_sage    = (const float*)d_in[6];
    const float* W_out     = (const float*)d_in[7];
    const float* b_out     = (const float*)d_in[8];

    float* out        = (float*)d_out;
    float* out_logits = out;                 // [N_DST, 2]
    float* out_scores = out + 2 * N_DST;     // [N_DST, 2]

    score_kernel<<<N_SRC / 8, 256>>>(x, W_dist, b_dist, out_scores);
    sage_kernel<<<N_DST / NB, 256>>>(x, neighbors, W_self, W_neigh, b_sage,
                                     W_out, b_out, out_logits);
}

// round 13
// speedup vs baseline: 2.0679x; 1.1600x over previous
#include <cuda_runtime.h>

#define N_SRC 60000
#define N_DST 30000
#define DEG   32
#define K_SEL 16
#define F     128
#define E     64
#define NB    8      // dst nodes per block in sage_kernel

// Scratch: per-source sigmoid(x . W_dist[:,0] + b_dist[0])
__device__ float g_sig[N_SRC];

// ---------------------------------------------------------------------------
// Kernel 1: warp-per-node. Computes g_sig for all 60000 source nodes and
// score_logits (both columns) for the 30000 dst nodes.
// ---------------------------------------------------------------------------
__global__ void score_kernel(const float* __restrict__ x,
                             const float* __restrict__ W_dist,
                             const float* __restrict__ b_dist,
                             float* __restrict__ out_scores) {
    __shared__ float sw[F * 2];
    int tid = threadIdx.x;
    if (tid < F * 2) sw[tid] = W_dist[tid];
    __syncthreads();

    int warp = tid >> 5;
    int lane = tid & 31;
    int node = blockIdx.x * (blockDim.x >> 5) + warp;
    if (node >= N_SRC) return;

    float4 x4 = reinterpret_cast<const float4*>(x + (size_t)node * F)[lane];
    int fb = lane * 4;
    float s0 = x4.x * sw[(fb + 0) * 2] + x4.y * sw[(fb + 1) * 2]
             + x4.z * sw[(fb + 2) * 2] + x4.w * sw[(fb + 3) * 2];
    float s1 = x4.x * sw[(fb + 0) * 2 + 1] + x4.y * sw[(fb + 1) * 2 + 1]
             + x4.z * sw[(fb + 2) * 2 + 1] + x4.w * sw[(fb + 3) * 2 + 1];

    #pragma unroll
    for (int off = 16; off; off >>= 1) {
        s0 += __shfl_xor_sync(0xFFFFFFFFu, s0, off);
        s1 += __shfl_xor_sync(0xFFFFFFFFu, s1, off);
    }

    if (lane == 0) {
        float l0 = s0 + b_dist[0];
        g_sig[node] = 1.0f / (1.0f + expf(-l0));
        if (node < N_DST) {
            out_scores[(size_t)node * 2 + 0] = l0;
            out_scores[(size_t)node * 2 + 1] = s1 + b_dist[1];
        }
    }
}

// ---------------------------------------------------------------------------
// Kernel 2: 8 dst nodes per 256-thread block.
//   phase 1: warp d scores + stable-ranks dst d's 32 neighbors (shuffle rank)
//   phase 2: warp d gathers its 16 selected rows (float4) + dst row
//   phase 3: MLP, thread=(eg:16 e-quad, dg:2 dst-group of 4, part:8 f-slice
//            of 16). Only 4 dst accumulators/thread -> low reg pressure,
//            4 blocks/SM. Weights read 2x per block (still 4x amortized).
//   phase 4: cross-part reduce + relu + tiny output projection
// ---------------------------------------------------------------------------
__global__ void __launch_bounds__(256, 4)
sage_kernel(const float* __restrict__ x,
            const int*   __restrict__ neighbors,
            const float* __restrict__ W_self,
            const float* __restrict__ W_neigh,
            const float* __restrict__ b_sage,
            const float* __restrict__ W_out,
            const float* __restrict__ b_out,
            float* __restrict__ out_logits) {
    int tid  = threadIdx.x;
    int warp = tid >> 5;
    int lane = tid & 31;
    int base = blockIdx.x * NB;

    __shared__ int    ssel[NB][K_SEL];
    __shared__ float  sxd[NB][F];
    __shared__ float  shn[NB][F];
    __shared__ float4 spart[8][NB][16];    // [part][d][eg]  16KB
    __shared__ float  sh[NB][E];

    // ---- phase 1: neighbor scoring + stable top-K rank (warp per dst) ----
    {
        int d  = warp;
        int nb = neighbors[(size_t)(base + d) * DEG + lane];
        float t  = g_sig[base + d];
        float df = fabsf(t - g_sig[nb]);
        int rank = 0;
        #pragma unroll
        for (int k = 0; k < DEG; k++) {
            float dk = __shfl_sync(0xFFFFFFFFu, df, k);
            rank += (dk < df) || (dk == df && k < lane);
        }
        // ranks are a permutation of 0..31: ranks 0..15 fill ssel exactly,
        // reproducing jax.lax.top_k(-diff) stable tie order.
        if (rank < K_SEL) ssel[d][rank] = nb;
    }
    // ssel[d] is produced and consumed by the same warp -> warp sync suffices.
    __syncwarp();

    // ---- phase 2: gather 16 selected rows + dst row (warp per dst) ----
    {
        int d = warp;
        float4 acc = make_float4(0.f, 0.f, 0.f, 0.f);
        #pragma unroll
        for (int s = 0; s < K_SEL; s++) {
            int r = ssel[d][s];
            float4 v = reinterpret_cast<const float4*>(x + (size_t)r * F)[lane];
            acc.x += v.x; acc.y += v.y; acc.z += v.z; acc.w += v.w;
        }
        float4 m;
        m.x = acc.x * (1.0f / K_SEL); m.y = acc.y * (1.0f / K_SEL);
        m.z = acc.z * (1.0f / K_SEL); m.w = acc.w * (1.0f / K_SEL);
        reinterpret_cast<float4*>(shn[d])[lane] = m;
        reinterpret_cast<float4*>(sxd[d])[lane] =
            reinterpret_cast<const float4*>(x + (size_t)(base + d) * F)[lane];
    }
    __syncthreads();

    // ---- phase 3: MLP partials. eg = 4 consecutive e (float4 weights),
    //      dg = which half of the 8 dsts, part = 16-wide f slice. ----
    {
        int eg   = tid & 15;
        int rest = tid >> 4;        // 0..15
        int dg   = rest & 1;        // 0..1  -> dsts dg*4 .. dg*4+3
        int part = rest >> 1;       // 0..7  -> f slice part*16 .. +16
        int d0   = dg * 4;
        const float4* Ws = reinterpret_cast<const float4*>(W_self);   // [f][16]
        const float4* Wn = reinterpret_cast<const float4*>(W_neigh);
        float4 a[4];
        #pragma unroll
        for (int dd = 0; dd < 4; dd++) a[dd] = make_float4(0.f, 0.f, 0.f, 0.f);

        #pragma unroll
        for (int f0 = 0; f0 < 16; f0++) {
            int f = part * 16 + f0;
            float4 ws = Ws[f * (E / 4) + eg];
            float4 wn = Wn[f * (E / 4) + eg];
            #pragma unroll
            for (int dd = 0; dd < 4; dd++) {
                float xs = sxd[d0 + dd][f];
                float hn = shn[d0 + dd][f];
                a[dd].x += xs * ws.x + hn * wn.x;
                a[dd].y += xs * ws.y + hn * wn.y;
                a[dd].z += xs * ws.z + hn * wn.z;
                a[dd].w += xs * ws.w + hn * wn.w;
            }
        }
        #pragma unroll
        for (int dd = 0; dd < 4; dd++) spart[part][d0 + dd][eg] = a[dd];
    }
    __syncthreads();

    // ---- phase 4a: reduce 8 parts, bias, relu (thread = (d, eg)) ----
    if (tid < NB * 16) {
        int d  = tid >> 4;
        int eg = tid & 15;
        float4 h = make_float4(0.f, 0.f, 0.f, 0.f);
        #pragma unroll
        for (int p = 0; p < 8; p++) {
            float4 v = spart[p][d][eg];
            h.x += v.x; h.y += v.y; h.z += v.z; h.w += v.w;
        }
        float4 bs = reinterpret_cast<const float4*>(b_sage)[eg];
        sh[d][eg * 4 + 0] = fmaxf(h.x + bs.x, 0.0f);
        sh[d][eg * 4 + 1] = fmaxf(h.y + bs.y, 0.0f);
        sh[d][eg * 4 + 2] = fmaxf(h.z + bs.z, 0.0f);
        sh[d][eg * 4 + 3] = fmaxf(h.w + bs.w, 0.0f);
    }
    __syncthreads();

    // ---- phase 4b: output projection (E=64 -> C=2) ----
    if (tid < NB * 2) {
        int d = tid >> 1;
        int c = tid & 1;
        float a = b_out[c];
        #pragma unroll
        for (int e = 0; e < E; e++) a += sh[d][e] * W_out[e * 2 + c];
        out_logits[(size_t)(base + d) * 2 + c] = a;
    }
}

// ---------------------------------------------------------------------------
extern "C" void kernel_launch(void* const* d_in, const int* in_sizes, int n_in,
                              void* d_out, int out_size) {
    const float* x         = (const float*)d_in[0];
    const int*   neighbors = (const int*)  d_in[1];
    const float* W_dist    = (const float*)d_in[2];
    const float* b_dist    = (const float*)d_in[3];
    const float* W_self    = (const float*)d_in[4];
    const float* W_neigh   = (const float*)d_in[5];
    const float* b_sage    = (const float*)d_in[6];
    const float* W_out     = (const float*)d_in[7];
    const float* b_out     = (const float*)d_in[8];

    float* out        = (float*)d_out;
    float* out_logits = out;                 // [N_DST, 2]
    float* out_scores = out + 2 * N_DST;     // [N_DST, 2]

    score_kernel<<<N_SRC / 8, 256>>>(x, W_dist, b_dist, out_scores);
    sage_kernel<<<N_DST / NB, 256>>>(x, neighbors, W_self, W_neigh, b_sage,
                                     W_out, b_out, out_logits);
}